// round 13
// baseline (speedup 1.0000x reference)
#include <cuda_runtime.h>
#include <math.h>

#define BB 32
#define HWT 12544          // 112*112
#define CC 256
#define HID 32
#define CHUNKS 32          // pool CTAs per batch -> 32 partials per batch
#define ROWS_PER_CHUNK (HWT / CHUNKS)     // 392
#define ROWS_PER_RG (ROWS_PER_CHUNK / 4)  // 98
#define F4_PER_ROW (CC / 4)               // 64
#define F4_PER_B ((size_t)HWT * F4_PER_ROW)   // 802816
#define BLOCKS3 98
#define F4_PER_BLOCK3 (F4_PER_B / BLOCKS3)    // 8192

__device__ float g_psum[BB][CHUNKS][CC];
__device__ float g_pmax[BB][CHUNKS][CC];

// Kernel 1: pooling with intra-CTA reduction -> 1 partial per (b,chunk).
// grid (CHUNKS, BB), 256 threads. Thread = (rg, c4). Streaming at 6.47TB/s
// (R1/R12-validated); smem reduce validated cost-free in R3.
__global__ void __launch_bounds__(256) pool_kernel(const float* __restrict__ x) {
    const int b = blockIdx.y;
    const int chunk = blockIdx.x;
    const int tid = threadIdx.x;
    const int c4 = tid & 63;
    const int rg = tid >> 6;

    __shared__ float4 s_sum[4][64];
    __shared__ float4 s_mx4[4][64];

    const size_t row0 = (size_t)b * HWT + (size_t)chunk * ROWS_PER_CHUNK + (size_t)rg * ROWS_PER_RG;
    const float4* __restrict__ xp = reinterpret_cast<const float4*>(x) + row0 * F4_PER_ROW + c4;

    float4 s = make_float4(0.f, 0.f, 0.f, 0.f);
    float4 m = make_float4(-INFINITY, -INFINITY, -INFINITY, -INFINITY);
    #pragma unroll 7
    for (int r = 0; r < ROWS_PER_RG; ++r) {
        float4 v = xp[(size_t)r * F4_PER_ROW];
        s.x += v.x; s.y += v.y; s.z += v.z; s.w += v.w;
        m.x = fmaxf(m.x, v.x); m.y = fmaxf(m.y, v.y);
        m.z = fmaxf(m.z, v.z); m.w = fmaxf(m.w, v.w);
    }
    s_sum[rg][c4] = s;
    s_mx4[rg][c4] = m;
    __syncthreads();

    if (rg == 0) {
        float4 a0 = s_sum[0][c4], a1 = s_sum[1][c4], a2 = s_sum[2][c4], a3 = s_sum[3][c4];
        float4 m0 = s_mx4[0][c4], m1 = s_mx4[1][c4], m2 = s_mx4[2][c4], m3 = s_mx4[3][c4];
        float4 ss = make_float4(a0.x + a1.x + a2.x + a3.x,
                                a0.y + a1.y + a2.y + a3.y,
                                a0.z + a1.z + a2.z + a3.z,
                                a0.w + a1.w + a2.w + a3.w);
        float4 mm = make_float4(fmaxf(fmaxf(m0.x, m1.x), fmaxf(m2.x, m3.x)),
                                fmaxf(fmaxf(m0.y, m1.y), fmaxf(m2.y, m3.y)),
                                fmaxf(fmaxf(m0.z, m1.z), fmaxf(m2.z, m3.z)),
                                fmaxf(fmaxf(m0.w, m1.w), fmaxf(m2.w, m3.w)));
        reinterpret_cast<float4*>(&g_psum[b][chunk][0])[c4] = ss;
        reinterpret_cast<float4*>(&g_pmax[b][chunk][0])[c4] = mm;
    }
}

// Kernel 2: redundant MLP head (every CTA, deterministic & identical) + scale
// stream. grid (BLOCKS3, BB), 256 thr, descending batch order.
__global__ void __launch_bounds__(256) scale_kernel(
    const float* __restrict__ x,
    const float* __restrict__ w1, const float* __restrict__ b1,
    const float* __restrict__ w2, const float* __restrict__ b2,
    float* __restrict__ out)
{
    const int b = (BB - 1) - blockIdx.y;   // descending
    const int tid = threadIdx.x;

    __shared__ float s_avg[CC];
    __shared__ float s_max[CC];
    __shared__ float s_h[2 * HID];
    __shared__ float s_scale[CC];

    // ---- head: reduce 32 partials for channel `tid` (coalesced L2 loads) ----
    {
        float sum = 0.f, mx = -INFINITY;
        #pragma unroll 8
        for (int q = 0; q < CHUNKS; ++q) {
            sum += __ldcg(&g_psum[b][q][tid]);
            mx = fmaxf(mx, __ldcg(&g_pmax[b][q][tid]));
        }
        s_avg[tid] = sum * (1.0f / (float)HWT);
        s_max[tid] = mx;
    }
    __syncthreads();

    {   // hidden layer: 64 outputs (avg 0..31, max 32..63), 4 threads/output
        int oi = tid >> 2;
        int part = tid & 3;
        int j = oi & (HID - 1);
        const float* pool = (oi < HID) ? s_avg : s_max;
        float acc = 0.f;
        #pragma unroll 16
        for (int i = part * 64; i < part * 64 + 64; ++i)
            acc += pool[i] * w1[i * HID + j];
        acc += __shfl_down_sync(0xffffffffu, acc, 1);
        acc += __shfl_down_sync(0xffffffffu, acc, 2);
        if (part == 0) s_h[oi] = fmaxf(acc + b1[j], 0.f);
    }
    __syncthreads();

    {   // output layer: 2*b2 + (hA+hM) @ w2, sigmoid
        float acc = 2.0f * b2[tid];
        #pragma unroll
        for (int j = 0; j < HID; ++j)
            acc += (s_h[j] + s_h[HID + j]) * w2[j * CC + tid];
        s_scale[tid] = 1.0f / (1.0f + expf(-acc));
    }
    __syncthreads();

    // ---- stream: out = x * scale ----
    const float4 sc = reinterpret_cast<const float4*>(s_scale)[tid & 63];
    const size_t base = (size_t)b * F4_PER_B + (size_t)blockIdx.x * F4_PER_BLOCK3;
    const float4* __restrict__ xi = reinterpret_cast<const float4*>(x) + base;
    float4* __restrict__ xo = reinterpret_cast<float4*>(out) + base;

    #pragma unroll 8
    for (int i = tid; i < F4_PER_BLOCK3; i += 256) {
        float4 v = __ldcs(xi + i);                 // last use: evict-first
        v.x *= sc.x; v.y *= sc.y; v.z *= sc.z; v.w *= sc.w;
        __stcs(xo + i, v);                         // streaming store
    }
}

extern "C" void kernel_launch(void* const* d_in, const int* in_sizes, int n_in,
                              void* d_out, int out_size) {
    const float* x  = (const float*)d_in[0];
    const float* w1 = (const float*)d_in[1];
    const float* b1 = (const float*)d_in[2];
    const float* w2 = (const float*)d_in[3];
    const float* b2 = (const float*)d_in[4];
    float* out = (float*)d_out;

    pool_kernel<<<dim3(CHUNKS, BB), 256>>>(x);
    scale_kernel<<<dim3(BLOCKS3, BB), 256>>>(x, w1, b1, w2, b2, out);
}

// round 15
// speedup vs baseline: 1.3069x; 1.3069x over previous
#include <cuda_runtime.h>
#include <math.h>

#define BB 32
#define HWT 12544          // 112*112
#define CC 256
#define HID 32
#define CHUNKS 32          // pool CTAs per batch -> 32 partials per batch
#define ROWS_PER_CHUNK (HWT / CHUNKS)     // 392
#define ROWS_PER_RG (ROWS_PER_CHUNK / 4)  // 98
#define F4_PER_ROW (CC / 4)               // 64
#define F4_PER_B ((size_t)HWT * F4_PER_ROW)   // 802816
#define BLOCKS3 98
#define F4_PER_BLOCK3 (F4_PER_B / BLOCKS3)    // 8192

__device__ float g_psum[BB][CHUNKS][CC];
__device__ float g_pmax[BB][CHUNKS][CC];
__device__ float g_scale[BB][CC];

// Kernel 1: pooling with intra-CTA smem reduction -> 1 partial per (b,chunk).
// grid (CHUNKS, BB), 256 threads. Streaming at 6.47TB/s (R12/R13-validated),
// smem reduce verified cost-free in R13. No atomics, no fences.
__global__ void __launch_bounds__(256) pool_kernel(const float* __restrict__ x) {
    const int b = blockIdx.y;
    const int chunk = blockIdx.x;
    const int tid = threadIdx.x;
    const int c4 = tid & 63;
    const int rg = tid >> 6;

    __shared__ float4 s_sum[4][64];
    __shared__ float4 s_mx4[4][64];

    const size_t row0 = (size_t)b * HWT + (size_t)chunk * ROWS_PER_CHUNK + (size_t)rg * ROWS_PER_RG;
    const float4* __restrict__ xp = reinterpret_cast<const float4*>(x) + row0 * F4_PER_ROW + c4;

    float4 s = make_float4(0.f, 0.f, 0.f, 0.f);
    float4 m = make_float4(-INFINITY, -INFINITY, -INFINITY, -INFINITY);
    #pragma unroll 7
    for (int r = 0; r < ROWS_PER_RG; ++r) {
        float4 v = xp[(size_t)r * F4_PER_ROW];
        s.x += v.x; s.y += v.y; s.z += v.z; s.w += v.w;
        m.x = fmaxf(m.x, v.x); m.y = fmaxf(m.y, v.y);
        m.z = fmaxf(m.z, v.z); m.w = fmaxf(m.w, v.w);
    }
    s_sum[rg][c4] = s;
    s_mx4[rg][c4] = m;
    __syncthreads();

    if (rg == 0) {
        float4 a0 = s_sum[0][c4], a1 = s_sum[1][c4], a2 = s_sum[2][c4], a3 = s_sum[3][c4];
        float4 m0 = s_mx4[0][c4], m1 = s_mx4[1][c4], m2 = s_mx4[2][c4], m3 = s_mx4[3][c4];
        float4 ss = make_float4(a0.x + a1.x + a2.x + a3.x,
                                a0.y + a1.y + a2.y + a3.y,
                                a0.z + a1.z + a2.z + a3.z,
                                a0.w + a1.w + a2.w + a3.w);
        float4 mm = make_float4(fmaxf(fmaxf(m0.x, m1.x), fmaxf(m2.x, m3.x)),
                                fmaxf(fmaxf(m0.y, m1.y), fmaxf(m2.y, m3.y)),
                                fmaxf(fmaxf(m0.z, m1.z), fmaxf(m2.z, m3.z)),
                                fmaxf(fmaxf(m0.w, m1.w), fmaxf(m2.w, m3.w)));
        reinterpret_cast<float4*>(&g_psum[b][chunk][0])[c4] = ss;
        reinterpret_cast<float4*>(&g_pmax[b][chunk][0])[c4] = mm;
    }
}

// Kernel 2: final reduction (32 partials) + dual-branch MLP + sigmoid.
// grid (BB), 256 threads. Reads only 2.1MB total -> ~2-3us.
__global__ void __launch_bounds__(256) mlp_kernel(const float* __restrict__ w1,
                                                  const float* __restrict__ b1,
                                                  const float* __restrict__ w2,
                                                  const float* __restrict__ b2) {
    const int b = blockIdx.x;
    const int c = threadIdx.x;

    float s = 0.f;
    float m = -INFINITY;
    #pragma unroll 8
    for (int p = 0; p < CHUNKS; ++p) {
        s += g_psum[b][p][c];
        m = fmaxf(m, g_pmax[b][p][c]);
    }

    __shared__ float s_avg[CC];
    __shared__ float s_max[CC];
    __shared__ float s_h[2 * HID];
    s_avg[c] = s * (1.0f / (float)HWT);
    s_max[c] = m;
    __syncthreads();

    {   // hidden layer: 64 outputs (avg 0..31, max 32..63), 4 threads/output
        int oi = c >> 2;
        int part = c & 3;
        int j = oi & (HID - 1);
        const float* pool = (oi < HID) ? s_avg : s_max;
        float acc = 0.f;
        #pragma unroll 16
        for (int i = part * 64; i < part * 64 + 64; ++i)
            acc += pool[i] * w1[i * HID + j];
        acc += __shfl_down_sync(0xffffffffu, acc, 1);
        acc += __shfl_down_sync(0xffffffffu, acc, 2);
        if (part == 0) s_h[oi] = fmaxf(acc + b1[j], 0.f);
    }
    __syncthreads();

    {   // output layer: out = 2*b2 + (hA+hM) @ w2, then sigmoid
        float acc = 2.0f * b2[c];
        #pragma unroll
        for (int j = 0; j < HID; ++j)
            acc += (s_h[j] + s_h[HID + j]) * w2[j * CC + c];
        g_scale[b][c] = 1.0f / (1.0f + expf(-acc));
    }
}

// Kernel 3: out = x * scale. grid (BLOCKS3, BB), 256 thr.
// Descending batch order + __ldcs/__stcs (R10/R12-validated: 124us).
__global__ void __launch_bounds__(256) scale_kernel(const float* __restrict__ x,
                                                    float* __restrict__ out) {
    const int b = (BB - 1) - blockIdx.y;   // descending
    const int tid = threadIdx.x;
    const float4 sc = reinterpret_cast<const float4*>(&g_scale[b][0])[tid & 63];

    const size_t base = (size_t)b * F4_PER_B + (size_t)blockIdx.x * F4_PER_BLOCK3;
    const float4* __restrict__ xi = reinterpret_cast<const float4*>(x) + base;
    float4* __restrict__ xo = reinterpret_cast<float4*>(out) + base;

    #pragma unroll 8
    for (int i = tid; i < F4_PER_BLOCK3; i += 256) {
        float4 v = __ldcs(xi + i);                 // last use: evict-first
        v.x *= sc.x; v.y *= sc.y; v.z *= sc.z; v.w *= sc.w;
        __stcs(xo + i, v);                         // streaming store
    }
}

extern "C" void kernel_launch(void* const* d_in, const int* in_sizes, int n_in,
                              void* d_out, int out_size) {
    const float* x  = (const float*)d_in[0];
    const float* w1 = (const float*)d_in[1];
    const float* b1 = (const float*)d_in[2];
    const float* w2 = (const float*)d_in[3];
    const float* b2 = (const float*)d_in[4];
    float* out = (float*)d_out;

    pool_kernel<<<dim3(CHUNKS, BB), 256>>>(x);
    mlp_kernel<<<BB, 256>>>(w1, b1, w2, b2);
    scale_kernel<<<dim3(BLOCKS3, BB), 256>>>(x, out);
}

// round 16
// speedup vs baseline: 1.3161x; 1.0070x over previous
#include <cuda_runtime.h>
#include <math.h>

#define BB 32
#define HWT 12544          // 112*112
#define CC 256
#define HID 32
#define CHUNKS 32          // pool CTAs per batch -> 32 partials per batch
#define ROWS_PER_CHUNK (HWT / CHUNKS)     // 392
#define ROWS_PER_RG (ROWS_PER_CHUNK / 4)  // 98
#define F4_PER_ROW (CC / 4)               // 64
#define F4_PER_B ((size_t)HWT * F4_PER_ROW)   // 802816
#define BLOCKS3 98
#define F4_PER_BLOCK3 (F4_PER_B / BLOCKS3)    // 8192

__device__ float g_psum[BB][CHUNKS][CC];
__device__ float g_pmax[BB][CHUNKS][CC];
__device__ float g_scale[BB][CC];

// Kernel 1: pooling with intra-CTA smem reduction -> 1 partial per (b,chunk).
// grid (CHUNKS, BB), 256 threads. 6.4TB/s validated. No atomics/fences.
__global__ void __launch_bounds__(256) pool_kernel(const float* __restrict__ x) {
    const int b = blockIdx.y;
    const int chunk = blockIdx.x;
    const int tid = threadIdx.x;
    const int c4 = tid & 63;
    const int rg = tid >> 6;

    __shared__ float4 s_sum[4][64];
    __shared__ float4 s_mx4[4][64];

    const size_t row0 = (size_t)b * HWT + (size_t)chunk * ROWS_PER_CHUNK + (size_t)rg * ROWS_PER_RG;
    const float4* __restrict__ xp = reinterpret_cast<const float4*>(x) + row0 * F4_PER_ROW + c4;

    float4 s = make_float4(0.f, 0.f, 0.f, 0.f);
    float4 m = make_float4(-INFINITY, -INFINITY, -INFINITY, -INFINITY);
    #pragma unroll 7
    for (int r = 0; r < ROWS_PER_RG; ++r) {
        float4 v = xp[(size_t)r * F4_PER_ROW];
        s.x += v.x; s.y += v.y; s.z += v.z; s.w += v.w;
        m.x = fmaxf(m.x, v.x); m.y = fmaxf(m.y, v.y);
        m.z = fmaxf(m.z, v.z); m.w = fmaxf(m.w, v.w);
    }
    s_sum[rg][c4] = s;
    s_mx4[rg][c4] = m;
    __syncthreads();

    if (rg == 0) {
        float4 a0 = s_sum[0][c4], a1 = s_sum[1][c4], a2 = s_sum[2][c4], a3 = s_sum[3][c4];
        float4 m0 = s_mx4[0][c4], m1 = s_mx4[1][c4], m2 = s_mx4[2][c4], m3 = s_mx4[3][c4];
        float4 ss = make_float4(a0.x + a1.x + a2.x + a3.x,
                                a0.y + a1.y + a2.y + a3.y,
                                a0.z + a1.z + a2.z + a3.z,
                                a0.w + a1.w + a2.w + a3.w);
        float4 mm = make_float4(fmaxf(fmaxf(m0.x, m1.x), fmaxf(m2.x, m3.x)),
                                fmaxf(fmaxf(m0.y, m1.y), fmaxf(m2.y, m3.y)),
                                fmaxf(fmaxf(m0.z, m1.z), fmaxf(m2.z, m3.z)),
                                fmaxf(fmaxf(m0.w, m1.w), fmaxf(m2.w, m3.w)));
        reinterpret_cast<float4*>(&g_psum[b][chunk][0])[c4] = ss;
        reinterpret_cast<float4*>(&g_pmax[b][chunk][0])[c4] = mm;
    }
    // Streaming + stores done: allow the dependent mlp grid to ramp up.
    cudaTriggerProgrammaticLaunchCompletion();
}

// Kernel 2: final reduction (32 partials) + dual-branch MLP + sigmoid.
// grid (BB), 256 threads. PDL secondary: sync at top, no prefetch.
__global__ void __launch_bounds__(256) mlp_kernel(const float* __restrict__ w1,
                                                  const float* __restrict__ b1,
                                                  const float* __restrict__ w2,
                                                  const float* __restrict__ b2) {
    cudaGridDependencySynchronize();   // wait for pool grid completion

    const int b = blockIdx.x;
    const int c = threadIdx.x;

    float s = 0.f;
    float m = -INFINITY;
    #pragma unroll 8
    for (int p = 0; p < CHUNKS; ++p) {
        s += g_psum[b][p][c];
        m = fmaxf(m, g_pmax[b][p][c]);
    }

    __shared__ float s_avg[CC];
    __shared__ float s_max[CC];
    __shared__ float s_h[2 * HID];
    s_avg[c] = s * (1.0f / (float)HWT);
    s_max[c] = m;
    __syncthreads();

    {   // hidden layer: 64 outputs (avg 0..31, max 32..63), 4 threads/output
        int oi = c >> 2;
        int part = c & 3;
        int j = oi & (HID - 1);
        const float* pool = (oi < HID) ? s_avg : s_max;
        float acc = 0.f;
        #pragma unroll 16
        for (int i = part * 64; i < part * 64 + 64; ++i)
            acc += pool[i] * w1[i * HID + j];
        acc += __shfl_down_sync(0xffffffffu, acc, 1);
        acc += __shfl_down_sync(0xffffffffu, acc, 2);
        if (part == 0) s_h[oi] = fmaxf(acc + b1[j], 0.f);
    }
    __syncthreads();

    {   // output layer: out = 2*b2 + (hA+hM) @ w2, then sigmoid
        float acc = 2.0f * b2[c];
        #pragma unroll
        for (int j = 0; j < HID; ++j)
            acc += (s_h[j] + s_h[HID + j]) * w2[j * CC + c];
        g_scale[b][c] = 1.0f / (1.0f + expf(-acc));
    }
    cudaTriggerProgrammaticLaunchCompletion();
}

// Kernel 3: out = x * scale. grid (BLOCKS3, BB), 256 thr.
// PDL secondary: sync at the very top (NO prefetch -> regs stay ~30).
// Descending batch order + __ldcs/__stcs (validated: ~124us).
__global__ void __launch_bounds__(256) scale_kernel(const float* __restrict__ x,
                                                    float* __restrict__ out) {
    cudaGridDependencySynchronize();   // wait for mlp grid completion

    const int b = (BB - 1) - blockIdx.y;   // descending
    const int tid = threadIdx.x;
    const float4 sc = reinterpret_cast<const float4*>(&g_scale[b][0])[tid & 63];

    const size_t base = (size_t)b * F4_PER_B + (size_t)blockIdx.x * F4_PER_BLOCK3;
    const float4* __restrict__ xi = reinterpret_cast<const float4*>(x) + base;
    float4* __restrict__ xo = reinterpret_cast<float4*>(out) + base;

    #pragma unroll 8
    for (int i = tid; i < F4_PER_BLOCK3; i += 256) {
        float4 v = __ldcs(xi + i);                 // last use: evict-first
        v.x *= sc.x; v.y *= sc.y; v.z *= sc.z; v.w *= sc.w;
        __stcs(xo + i, v);                         // streaming store
    }
}

extern "C" void kernel_launch(void* const* d_in, const int* in_sizes, int n_in,
                              void* d_out, int out_size) {
    const float* x  = (const float*)d_in[0];
    const float* w1 = (const float*)d_in[1];
    const float* b1 = (const float*)d_in[2];
    const float* w2 = (const float*)d_in[3];
    const float* b2 = (const float*)d_in[4];
    float* out = (float*)d_out;

    pool_kernel<<<dim3(CHUNKS, BB), 256>>>(x);

    cudaLaunchAttribute attr[1];
    attr[0].id = cudaLaunchAttributeProgrammaticStreamSerialization;
    attr[0].val.programmaticStreamSerializationAllowed = 1;

    {   // mlp as PDL secondary
        cudaLaunchConfig_t cfg = {};
        cfg.gridDim = dim3(BB, 1, 1);
        cfg.blockDim = dim3(256, 1, 1);
        cfg.stream = 0;
        cfg.attrs = attr;
        cfg.numAttrs = 1;
        cudaLaunchKernelEx(&cfg, mlp_kernel, w1, b1, w2, b2);
    }
    {   // scale as PDL secondary
        cudaLaunchConfig_t cfg = {};
        cfg.gridDim = dim3(BLOCKS3, BB, 1);
        cfg.blockDim = dim3(256, 1, 1);
        cfg.stream = 0;
        cfg.attrs = attr;
        cfg.numAttrs = 1;
        cudaLaunchKernelEx(&cfg, scale_kernel, x, out);
    }
}